// round 8
// baseline (speedup 1.0000x reference)
#include <cuda_runtime.h>
#include <cstdint>

// SuperchargingBKT — round 7: two-kernel split.
//
// Evidence: R2-R6 (occupancy x, L1-traffic cuts, cp.async MLP) all pin at
// 65±3us, issue 17-21%, no pipe >60%. The fused scan can't saturate the
// gather (l1tex wavefront) pipe: warp count capped by smem/regs, gathers
// chained to the recurrence. Split:
//   K1: flat coefficient materialization. 1 thread/element, no smem, ~40
//       regs -> max occupancy, pure gather throughput. obs packed in
//       sign(c1). Coalesced float4 store to 64MB __device__ scratch
//       (L2-resident: 64MB < 126MB L2).
//   K2: warp-per-row 2x2 projective matrix scan. cp.async-coalesced load of
//       the warp's 512 coeffs into padded smem (conflict-aware), scan +
//       replay, smem-bounced coalesced output.
//
// Inputs (metadata order):
//  0 pL0_logit [K] f32   4 pS_logit [K] f32    8 observations [B,T] i32
//  1 pT_logit  [K] f32   5 omega    [P] f32    9 kc_ids       [B,T] i32
//  2 pF_logit  [K] f32   6 sigma    [P] f32   10 problem_ids  [B,T] i32
//  3 pG_logit  [K] f32   7 ability  [S,4] f32 11 student_ids  [B,T] i32
// Output: p_correct [B,T] f32

constexpr int T_LEN = 512;
constexpr int SEG   = 16;              // steps per lane (32 lanes x 16)
constexpr int B_CAP = 8192;
constexpr int K_CAP = 1024;            // K = 1000
constexpr int P_CAP = 50048;           // P = 50000

__device__ float4 g_kcpack[K_CAP];     // (pT,pF,pG,pS) logits per KC
__device__ float2 g_pspack[P_CAP];     // (omega,sigma) per problem
__device__ float4 g_coeff[B_CAP * T_LEN];   // 64MB scratch: (±c1,c2,c3,c4)

__device__ __forceinline__ float sigmoidf(float x) {
    return __fdividef(1.0f, 1.0f + __expf(-x));
}

__device__ __forceinline__ void cp_async16(uint32_t dst, const void* src) {
    asm volatile("cp.async.cg.shared.global [%0], [%1], 16;\n"
                 :: "r"(dst), "l"(src));
}
__device__ __forceinline__ void cp_commit() {
    asm volatile("cp.async.commit_group;\n" ::: "memory");
}
__device__ __forceinline__ void cp_wait_all() {
    asm volatile("cp.async.wait_group 0;\n" ::: "memory");
}

// ---------------------------------------------------------------------------
__global__ void pack_tables(
    const float* __restrict__ pT_logit, const float* __restrict__ pF_logit,
    const float* __restrict__ pG_logit, const float* __restrict__ pS_logit,
    const float* __restrict__ omega,    const float* __restrict__ sigma,
    int K, int P)
{
    int i = blockIdx.x * blockDim.x + threadIdx.x;
    if (i < K)
        g_kcpack[i] = make_float4(pT_logit[i], pF_logit[i], pG_logit[i], pS_logit[i]);
    if (i < P)
        g_pspack[i] = make_float2(omega[i], sigma[i]);
}

// ---------------------------------------------------------------------------
// K1: flat coefficient materialization. Max occupancy, latency-immune.
__global__ void __launch_bounds__(256)
coeff_kernel(
    const float4* __restrict__ ability,
    const int*  __restrict__ obs,
    const int*  __restrict__ kc,
    const int*  __restrict__ pid,
    const int*  __restrict__ sid,
    int N)
{
    int e = blockIdx.x * blockDim.x + threadIdx.x;
    if (e >= N) return;

    int k = kc[e];
    int p = pid[e];
    int s = sid[e];
    int o = obs[e];

    float4 th  = __ldg(ability + s);
    float4 kcp = __ldg(&g_kcpack[k]);      // 16KB table, L1-resident
    float2 psp = __ldg(&g_pspack[p]);

    float pT = sigmoidf(kcp.x + th.x);
    float pF = sigmoidf(kcp.y - th.y);
    float pG = sigmoidf(kcp.z + psp.x + th.z);
    float pS = sigmoidf(kcp.w + psp.y - th.w);

    bool ob = (o != 0);
    float pom = ob ? (1.0f - pS) : pS;     // P(y | mastered)
    float pou = ob ? pG : (1.0f - pG);     // P(y | unmastered)
    float c1 = (1.0f - pF) * pom;          // c1 > 0 strictly
    float c2 = pT * pou;
    float c3 = pF * pom;
    float c4 = (1.0f - pT) * pou;

    g_coeff[e] = make_float4(ob ? c1 : -c1, c2, c3, c4);
}

// ---------------------------------------------------------------------------
// K2: warp-per-row scan over L2-resident coefficients.
constexpr int K2_THREADS = 128;                     // 4 warps/CTA
constexpr int CBUF_F4    = T_LEN + (T_LEN >> 3);    // 576 float4 (pad 1/8)
constexpr int K2_SMEM    = 4 * CBUF_F4 * 16;        // 36864 B

__device__ __forceinline__ int padi(int s) { return s + (s >> 3); }

__global__ void __launch_bounds__(K2_THREADS)
scan_kernel(
    const float* __restrict__ pL0_logit,
    const int*  __restrict__ kc,
    float* __restrict__ out,
    int B)
{
    extern __shared__ float4 smem[];
    const int tid   = threadIdx.x;
    const int lane  = tid & 31;
    const int wInB  = tid >> 5;
    const int warp  = blockIdx.x * (K2_THREADS / 32) + wInB;
    if (warp >= B) return;

    float4* cbuf = smem + wInB * CBUF_F4;      // this warp's padded cache
    const int base = warp * T_LEN;

    // ---- coalesced cp.async of the warp's 512 coeffs into padded smem ----
    const uint32_t cbase = (uint32_t)__cvta_generic_to_shared(cbuf);
#pragma unroll
    for (int w = 0; w < 16; ++w) {
        int j = w * 32 + lane;                 // coalesced global index
        cp_async16(cbase + padi(j) * 16u, &g_coeff[base + j]);
    }
    cp_commit();

    // initial state from pL0 at first KC (overlaps with cp.async)
    float pL0 = sigmoidf(__ldg(pL0_logit + __ldg(kc + base)));

    cp_wait_all();
    __syncwarp();

    // ---- pass 1: per-lane segment matrix product -------------------------
    float a00 = 1.f, a01 = 0.f, a10 = 0.f, a11 = 1.f;
#pragma unroll
    for (int i = 0; i < SEG; ++i) {
        int s = lane * SEG + i;
        float4 cc = cbuf[padi(s)];
        float c1 = fabsf(cc.x);
        float n00 = fmaf(cc.w, a00, cc.z * a10);   // M = [[c4,c3],[c2,c1]]
        float n01 = fmaf(cc.w, a01, cc.z * a11);
        float n10 = fmaf(cc.y, a00, c1 * a10);
        float n11 = fmaf(cc.y, a01, c1 * a11);
        a00 = n00; a01 = n01; a10 = n10; a11 = n11;
        if ((i & 7) == 7) {
            float r = __fdividef(1.0f, a00 + a01 + a10 + a11);
            a00 *= r; a01 *= r; a10 *= r; a11 *= r;
        }
    }

    // ---- inclusive warp scan of segment matrices -------------------------
#pragma unroll
    for (int d = 1; d < 32; d <<= 1) {
        float b00 = __shfl_up_sync(0xFFFFFFFFu, a00, d);
        float b01 = __shfl_up_sync(0xFFFFFFFFu, a01, d);
        float b10 = __shfl_up_sync(0xFFFFFFFFu, a10, d);
        float b11 = __shfl_up_sync(0xFFFFFFFFu, a11, d);
        if (lane >= d) {
            float n00 = fmaf(a00, b00, a01 * b10);   // mine(later)*other(earlier)
            float n01 = fmaf(a00, b01, a01 * b11);
            float n10 = fmaf(a10, b00, a11 * b10);
            float n11 = fmaf(a10, b01, a11 * b11);
            float r = __fdividef(1.0f, n00 + n01 + n10 + n11);
            a00 = n00 * r; a01 = n01 * r; a10 = n10 * r; a11 = n11 * r;
        }
    }

    // exclusive prefix
    float e00 = __shfl_up_sync(0xFFFFFFFFu, a00, 1);
    float e01 = __shfl_up_sync(0xFFFFFFFFu, a01, 1);
    float e10 = __shfl_up_sync(0xFFFFFFFFu, a10, 1);
    float e11 = __shfl_up_sync(0xFFFFFFFFu, a11, 1);
    if (lane == 0) { e00 = 1.f; e01 = 0.f; e10 = 0.f; e11 = 1.f; }

    float hu0 = 1.0f - pL0;
    float hm0 = pL0;
    float hu = fmaf(e00, hu0, e01 * hm0);
    float hm = fmaf(e10, hu0, e11 * hm0);
    float rs = __fdividef(1.0f, hu + hm);
    hu *= rs; hm *= rs;

    // ---- pass 2: replay; overwrite cbuf[.].x with pc ---------------------
#pragma unroll
    for (int i = 0; i < SEG; ++i) {
        int s = lane * SEG + i;
        int a = padi(s);
        float4 cc = cbuf[a];
        bool o = (cc.x > 0.0f);
        float c1 = fabsf(cc.x);
        float nm = fmaf(c1,   hm, cc.y * hu);
        float nu = fmaf(cc.z, hm, cc.w * hu);
        float r  = __fdividef(1.0f, nm + nu);
        hm = nm * r;
        hu = nu * r;
        float pom = c1 + cc.z;                 // = 1-pS if o else pS
        float pou = cc.y + cc.w;               // = pG   if o else 1-pG
        float c5 = o ? pom : (1.0f - pom);     // 1-pS
        float c6 = o ? pou : (1.0f - pou);     // pG
        reinterpret_cast<float*>(cbuf)[a * 4] = fmaf(c5, hm, c6 * hu);
    }
    __syncwarp();

    // ---- coalesced writeout from smem ------------------------------------
    const float* cf = reinterpret_cast<const float*>(cbuf);
#pragma unroll
    for (int w = 0; w < 16; ++w) {
        int j = w * 32 + lane;
        out[base + j] = cf[padi(j) * 4];
    }
}

// ---------------------------------------------------------------------------
extern "C" void kernel_launch(void* const* d_in, const int* in_sizes, int n_in,
                              void* d_out, int out_size) {
    const float* pL0 = (const float*)d_in[0];
    const float* pT  = (const float*)d_in[1];
    const float* pF  = (const float*)d_in[2];
    const float* pG  = (const float*)d_in[3];
    const float* pS  = (const float*)d_in[4];
    const float* om  = (const float*)d_in[5];
    const float* sg  = (const float*)d_in[6];
    const float4* ab = (const float4*)d_in[7];
    const int* obs = (const int*)d_in[8];
    const int* kc  = (const int*)d_in[9];
    const int* pid = (const int*)d_in[10];
    const int* sid = (const int*)d_in[11];
    float* out = (float*)d_out;

    int K = in_sizes[0];                  // 1000
    int P = in_sizes[5];                  // 50000
    int N = in_sizes[8];                  // B*T = 4194304
    int B = N / T_LEN;                    // 8192
    if (K > K_CAP) K = K_CAP;
    if (P > P_CAP) P = P_CAP;

    cudaFuncSetAttribute(scan_kernel,
                         cudaFuncAttributeMaxDynamicSharedMemorySize, K2_SMEM);

    int n = (K > P) ? K : P;
    pack_tables<<<(n + 255) / 256, 256>>>(pT, pF, pG, pS, om, sg, K, P);

    coeff_kernel<<<(N + 255) / 256, 256>>>(ab, obs, kc, pid, sid, N);

    int rows_per_cta = K2_THREADS / 32;
    scan_kernel<<<(B + rows_per_cta - 1) / rows_per_cta, K2_THREADS, K2_SMEM>>>(
        pL0, kc, out, B);
}

// round 10
// speedup vs baseline: 1.3357x; 1.3357x over previous
#include <cuda_runtime.h>
#include <cuda_fp16.h>
#include <cstdint>

// SuperchargingBKT — round 9 (= round 8 retry; R8 bench died to infra).
//
// Unified model (fits R2-R7): runtime tracks the chip's L2 random-sector
// request service, ~invariant to occupancy / L1 traffic / issue path
// (R3,R4,R6 flat; R7's +128MB scratch made it slower). So: cut requests.
//   * (omega,sigma) packed to __half2 (4B) -> 200KB table, ~L1-resident
//     (smem held to 16KB/CTA so L1D ~196KB) -> its 4.2M random L2 requests
//     mostly disappear. Precision cost ~1e-4 rel (tol 1e-3).
//   * kc table (16KB float4) staged in smem (LDS, no L2 traffic).
//   * ability stays fp32x4 LDG (the one irreducible random L2 request/elem).
//   * coefficients in registers (R2 layout, 2 CTAs x 256 thr, ~122 regs).
//
// Inputs (metadata order):
//  0 pL0_logit [K] f32   4 pS_logit [K] f32    8 observations [B,T] i32
//  1 pT_logit  [K] f32   5 omega    [P] f32    9 kc_ids       [B,T] i32
//  2 pF_logit  [K] f32   6 sigma    [P] f32   10 problem_ids  [B,T] i32
//  3 pG_logit  [K] f32   7 ability  [S,4] f32 11 student_ids  [B,T] i32
// Output: p_correct [B,T] f32

constexpr int T_LEN = 512;
constexpr int SEG   = 16;              // steps per lane (32 lanes x 16 = 512)
constexpr int THREADS = 256;
constexpr int K_CAP = 1024;            // K = 1000
constexpr int P_CAP = 50048;           // P = 50000

__device__ float4  g_kcpack[K_CAP];    // (pT,pF,pG,pS) logits per KC
__device__ __half2 g_pshalf[P_CAP];    // (omega,sigma) per problem, fp16

__device__ __forceinline__ float sigmoidf(float x) {
    return __fdividef(1.0f, 1.0f + __expf(-x));
}

__global__ void pack_tables(
    const float* __restrict__ pT_logit, const float* __restrict__ pF_logit,
    const float* __restrict__ pG_logit, const float* __restrict__ pS_logit,
    const float* __restrict__ omega,    const float* __restrict__ sigma,
    int K, int P)
{
    int i = blockIdx.x * blockDim.x + threadIdx.x;
    if (i < K)
        g_kcpack[i] = make_float4(pT_logit[i], pF_logit[i], pG_logit[i], pS_logit[i]);
    if (i < P)
        g_pshalf[i] = __floats2half2_rn(omega[i], sigma[i]);
}

__global__ void __launch_bounds__(THREADS, 2)
bkt_warp_scan(
    const float* __restrict__ pL0_logit,
    const float4* __restrict__ ability,
    const int*  __restrict__ obs,
    const int*  __restrict__ kc,
    const int*  __restrict__ pid,
    const int*  __restrict__ sid,
    float* __restrict__ out,
    int B, int K)
{
    __shared__ float4 kcTab[K_CAP];        // 16KB -> leaves ~196KB L1D

    const int tid  = threadIdx.x;
    const int lane = tid & 31;
    const int warp = (blockIdx.x * blockDim.x + tid) >> 5;

    for (int i = tid; i < K; i += THREADS) kcTab[i] = g_kcpack[i];
    __syncthreads();

    if (warp >= B) return;

    const int base = warp * T_LEN;
    const int s0   = base + lane * SEG;

    float C1[SEG], C2[SEG], C3[SEG], C4[SEG];
    unsigned obits = 0;

    // A maps segment-start state (hu,hm) -> state after processed steps.
    float a00 = 1.f, a01 = 0.f, a10 = 0.f, a11 = 1.f;

    // ---------------- pass 1: coefficients + segment matrix product --------
#pragma unroll
    for (int q = 0; q < SEG / 4; ++q) {
        const int o4i = s0 + 4 * q;
        int4 kv = *reinterpret_cast<const int4*>(kc  + o4i);
        int4 pv = *reinterpret_cast<const int4*>(pid + o4i);
        int4 sv = *reinterpret_cast<const int4*>(sid + o4i);
        int4 ov = *reinterpret_cast<const int4*>(obs + o4i);
        int kk[4] = {kv.x, kv.y, kv.z, kv.w};
        int pp[4] = {pv.x, pv.y, pv.z, pv.w};
        int ssx[4]= {sv.x, sv.y, sv.z, sv.w};
        int oo[4] = {ov.x, ov.y, ov.z, ov.w};

#pragma unroll
        for (int j = 0; j < 4; ++j) {
            const int i = 4 * q + j;
            float4 th  = __ldg(ability + ssx[j]);          // the L2 random req
            float4 kcp = kcTab[kk[j]];                     // LDS (no L2)
            float2 psp = __half22float2(__ldg(&g_pshalf[pp[j]]));  // ~L1 hit
            float pT = sigmoidf(kcp.x + th.x);
            float pF = sigmoidf(kcp.y - th.y);
            float pG = sigmoidf(kcp.z + psp.x + th.z);
            float pS = sigmoidf(kcp.w + psp.y - th.w);
            bool o = (oo[j] != 0);
            float pom = o ? (1.0f - pS) : pS;      // P(y | mastered)
            float pou = o ? pG : (1.0f - pG);      // P(y | unmastered)
            float c1 = (1.0f - pF) * pom;
            float c2 = pT * pou;
            float c3 = pF * pom;
            float c4 = (1.0f - pT) * pou;
            C1[i] = c1; C2[i] = c2; C3[i] = c3; C4[i] = c4;
            obits |= (o ? 1u : 0u) << i;

            // A = M * A,  M = [[c4,c3],[c2,c1]]
            float n00 = fmaf(c4, a00, c3 * a10);
            float n01 = fmaf(c4, a01, c3 * a11);
            float n10 = fmaf(c2, a00, c1 * a10);
            float n11 = fmaf(c2, a01, c1 * a11);
            a00 = n00; a01 = n01; a10 = n10; a11 = n11;
        }
        if (q & 1) {
            // normalize every 8 steps (projective scale is irrelevant)
            float r = __fdividef(1.0f, a00 + a01 + a10 + a11);
            a00 *= r; a01 *= r; a10 *= r; a11 *= r;
        }
    }

    // ------------- inclusive warp scan of segment matrices -----------------
#pragma unroll
    for (int d = 1; d < 32; d <<= 1) {
        float b00 = __shfl_up_sync(0xFFFFFFFFu, a00, d);
        float b01 = __shfl_up_sync(0xFFFFFFFFu, a01, d);
        float b10 = __shfl_up_sync(0xFFFFFFFFu, a10, d);
        float b11 = __shfl_up_sync(0xFFFFFFFFu, a11, d);
        if (lane >= d) {
            float n00 = fmaf(a00, b00, a01 * b10);   // mine(later)*other(earlier)
            float n01 = fmaf(a00, b01, a01 * b11);
            float n10 = fmaf(a10, b00, a11 * b10);
            float n11 = fmaf(a10, b01, a11 * b11);
            float r = __fdividef(1.0f, n00 + n01 + n10 + n11);
            a00 = n00 * r; a01 = n01 * r; a10 = n10 * r; a11 = n11 * r;
        }
    }

    // exclusive prefix
    float e00 = __shfl_up_sync(0xFFFFFFFFu, a00, 1);
    float e01 = __shfl_up_sync(0xFFFFFFFFu, a01, 1);
    float e10 = __shfl_up_sync(0xFFFFFFFFu, a10, 1);
    float e11 = __shfl_up_sync(0xFFFFFFFFu, a11, 1);
    if (lane == 0) { e00 = 1.f; e01 = 0.f; e10 = 0.f; e11 = 1.f; }

    // initial state from pL0 at first KC (uniform broadcast load)
    float pL0 = sigmoidf(__ldg(pL0_logit + __ldg(kc + base)));
    float hu0 = 1.0f - pL0;
    float hm0 = pL0;
    float hu = fmaf(e00, hu0, e01 * hm0);
    float hm = fmaf(e10, hu0, e11 * hm0);
    float rs = __fdividef(1.0f, hu + hm);
    hu *= rs; hm *= rs;

    // ---------------- pass 2: replay segment, emit p_correct ---------------
    float* op = out + s0;
#pragma unroll
    for (int q = 0; q < SEG / 4; ++q) {
        float4 res;
        float* r4 = reinterpret_cast<float*>(&res);
#pragma unroll
        for (int j = 0; j < 4; ++j) {
            const int i = 4 * q + j;
            float nm = fmaf(C1[i], hm, C2[i] * hu);
            float nu = fmaf(C3[i], hm, C4[i] * hu);
            float r  = __fdividef(1.0f, nm + nu);
            hm = nm * r;
            hu = nu * r;
            bool o = (obits >> i) & 1u;
            float pom = C1[i] + C3[i];             // = 1-pS if o else pS
            float pou = C2[i] + C4[i];             // = pG   if o else 1-pG
            float c5 = o ? pom : (1.0f - pom);     // 1-pS
            float c6 = o ? pou : (1.0f - pou);     // pG
            r4[j] = fmaf(c5, hm, c6 * hu);
        }
        *reinterpret_cast<float4*>(op + 4 * q) = res;
    }
}

extern "C" void kernel_launch(void* const* d_in, const int* in_sizes, int n_in,
                              void* d_out, int out_size) {
    const float* pL0 = (const float*)d_in[0];
    const float* pT  = (const float*)d_in[1];
    const float* pF  = (const float*)d_in[2];
    const float* pG  = (const float*)d_in[3];
    const float* pS  = (const float*)d_in[4];
    const float* om  = (const float*)d_in[5];
    const float* sg  = (const float*)d_in[6];
    const float4* ab = (const float4*)d_in[7];
    const int* obs = (const int*)d_in[8];
    const int* kc  = (const int*)d_in[9];
    const int* pid = (const int*)d_in[10];
    const int* sid = (const int*)d_in[11];
    float* out = (float*)d_out;

    int K = in_sizes[0];                  // 1000
    int P = in_sizes[5];                  // 50000
    int B = in_sizes[8] / T_LEN;          // 8192 rows
    if (K > K_CAP) K = K_CAP;
    if (P > P_CAP) P = P_CAP;

    int n = (K > P) ? K : P;
    if (n < 1) n = 1;
    pack_tables<<<(n + 511) / 512, 512>>>(pT, pF, pG, pS, om, sg, K, P);

    int warps_per_block = THREADS / 32;
    int grid = (B + warps_per_block - 1) / warps_per_block;
    bkt_warp_scan<<<grid, THREADS>>>(pL0, ab, obs, kc, pid, sid, out, B, K);
}

// round 11
// speedup vs baseline: 1.3371x; 1.0011x over previous
#include <cuda_runtime.h>
#include <cuda_fp16.h>
#include <cstdint>

// SuperchargingBKT — round 10: 2 warps per row (SEG=8), full gather
// front-loading.
//
// R9 (fp16 pspack -> L1-resident) gave 65->59.5us and showed DRAM is pure
// streaming; nothing saturated -> residual is the per-warp serial chain of
// (idx -> gather -> sigmoid -> matmul) blocks. R10 halves that chain: each
// row is split across 2 warps (256 steps each, 8/lane). Register budget now
// lets ALL 8 ability/ps gathers issue before any compute (max per-warp MLP).
// Cross-warp prefix combine: one 2x2 matrix via smem + one __syncthreads.
// Keeps R9 wins: kc table in smem (16KB), (omega,sigma) as __half2 table.
//
// Inputs (metadata order):
//  0 pL0_logit [K] f32   4 pS_logit [K] f32    8 observations [B,T] i32
//  1 pT_logit  [K] f32   5 omega    [P] f32    9 kc_ids       [B,T] i32
//  2 pF_logit  [K] f32   6 sigma    [P] f32   10 problem_ids  [B,T] i32
//  3 pG_logit  [K] f32   7 ability  [S,4] f32 11 student_ids  [B,T] i32
// Output: p_correct [B,T] f32

constexpr int T_LEN = 512;
constexpr int SEG   = 8;               // steps per lane (2 warps x 32 x 8)
constexpr int HALF  = 256;             // steps per warp
constexpr int THREADS = 256;           // 8 warps = 4 rows per CTA
constexpr int ROWS_PER_CTA = 4;
constexpr int K_CAP = 1024;            // K = 1000
constexpr int P_CAP = 50048;           // P = 50000

__device__ float4  g_kcpack[K_CAP];    // (pT,pF,pG,pS) logits per KC
__device__ __half2 g_pshalf[P_CAP];    // (omega,sigma) per problem, fp16

__device__ __forceinline__ float sigmoidf(float x) {
    return __fdividef(1.0f, 1.0f + __expf(-x));
}

__global__ void pack_tables(
    const float* __restrict__ pT_logit, const float* __restrict__ pF_logit,
    const float* __restrict__ pG_logit, const float* __restrict__ pS_logit,
    const float* __restrict__ omega,    const float* __restrict__ sigma,
    int K, int P)
{
    int i = blockIdx.x * blockDim.x + threadIdx.x;
    if (i < K)
        g_kcpack[i] = make_float4(pT_logit[i], pF_logit[i], pG_logit[i], pS_logit[i]);
    if (i < P)
        g_pshalf[i] = __floats2half2_rn(omega[i], sigma[i]);
}

__global__ void __launch_bounds__(THREADS, 2)
bkt_warp_scan(
    const float* __restrict__ pL0_logit,
    const float4* __restrict__ ability,
    const int*  __restrict__ obs,
    const int*  __restrict__ kc,
    const int*  __restrict__ pid,
    const int*  __restrict__ sid,
    float* __restrict__ out,
    int B, int K)
{
    __shared__ float4 kcTab[K_CAP];              // 16KB
    __shared__ float4 w0tot[ROWS_PER_CTA];       // warp0 total matrix per row

    const int tid  = threadIdx.x;
    const int lane = tid & 31;
    const int wid  = tid >> 5;                   // 0..7
    const int rowInCta  = wid >> 1;              // 0..3
    const int warpInRow = wid & 1;               // 0 = steps 0-255, 1 = 256-511
    const int row  = blockIdx.x * ROWS_PER_CTA + rowInCta;

    for (int i = tid; i < K; i += THREADS) kcTab[i] = g_kcpack[i];
    __syncthreads();

    const int base = row * T_LEN;
    const int s0   = base + warpInRow * HALF + lane * SEG;

    // ---- front-load ALL indices and gathers for this lane's 8 steps ------
    int4 kv0 = *reinterpret_cast<const int4*>(kc  + s0);
    int4 kv1 = *reinterpret_cast<const int4*>(kc  + s0 + 4);
    int4 pv0 = *reinterpret_cast<const int4*>(pid + s0);
    int4 pv1 = *reinterpret_cast<const int4*>(pid + s0 + 4);
    int4 sv0 = *reinterpret_cast<const int4*>(sid + s0);
    int4 sv1 = *reinterpret_cast<const int4*>(sid + s0 + 4);
    int4 ov0 = *reinterpret_cast<const int4*>(obs + s0);
    int4 ov1 = *reinterpret_cast<const int4*>(obs + s0 + 4);

    int kk[SEG] = {kv0.x, kv0.y, kv0.z, kv0.w, kv1.x, kv1.y, kv1.z, kv1.w};
    int pp[SEG] = {pv0.x, pv0.y, pv0.z, pv0.w, pv1.x, pv1.y, pv1.z, pv1.w};
    int ssx[SEG]= {sv0.x, sv0.y, sv0.z, sv0.w, sv1.x, sv1.y, sv1.z, sv1.w};
    unsigned obits = 0;
    {
        int oo[SEG] = {ov0.x, ov0.y, ov0.z, ov0.w, ov1.x, ov1.y, ov1.z, ov1.w};
#pragma unroll
        for (int i = 0; i < SEG; ++i) obits |= (oo[i] != 0 ? 1u : 0u) << i;
    }

    float4  th[SEG];
    __half2 ph[SEG];
#pragma unroll
    for (int i = 0; i < SEG; ++i) th[i] = __ldg(ability + ssx[i]);   // 8 in flight
#pragma unroll
    for (int i = 0; i < SEG; ++i) ph[i] = __ldg(&g_pshalf[pp[i]]);

    // initial state from pL0 at first KC (uniform broadcast load)
    float pL0 = sigmoidf(__ldg(pL0_logit + __ldg(kc + base)));

    // ---- pass 1: coefficients + per-lane segment matrix product ----------
    float C1[SEG], C2[SEG], C3[SEG], C4[SEG];
    float a00 = 1.f, a01 = 0.f, a10 = 0.f, a11 = 1.f;
#pragma unroll
    for (int i = 0; i < SEG; ++i) {
        float4 kcp = kcTab[kk[i]];               // LDS.128
        float2 psp = __half22float2(ph[i]);
        float pT = sigmoidf(kcp.x + th[i].x);
        float pF = sigmoidf(kcp.y - th[i].y);
        float pG = sigmoidf(kcp.z + psp.x + th[i].z);
        float pS = sigmoidf(kcp.w + psp.y - th[i].w);
        bool o = (obits >> i) & 1u;
        float pom = o ? (1.0f - pS) : pS;        // P(y | mastered)
        float pou = o ? pG : (1.0f - pG);        // P(y | unmastered)
        float c1 = (1.0f - pF) * pom;
        float c2 = pT * pou;
        float c3 = pF * pom;
        float c4 = (1.0f - pT) * pou;
        C1[i] = c1; C2[i] = c2; C3[i] = c3; C4[i] = c4;

        // A = M * A,  M = [[c4,c3],[c2,c1]]
        float n00 = fmaf(c4, a00, c3 * a10);
        float n01 = fmaf(c4, a01, c3 * a11);
        float n10 = fmaf(c2, a00, c1 * a10);
        float n11 = fmaf(c2, a01, c1 * a11);
        a00 = n00; a01 = n01; a10 = n10; a11 = n11;
    }
    {   // one normalization per 8-step segment
        float r = __fdividef(1.0f, a00 + a01 + a10 + a11);
        a00 *= r; a01 *= r; a10 *= r; a11 *= r;
    }

    // ---- inclusive warp scan of segment matrices -------------------------
#pragma unroll
    for (int d = 1; d < 32; d <<= 1) {
        float b00 = __shfl_up_sync(0xFFFFFFFFu, a00, d);
        float b01 = __shfl_up_sync(0xFFFFFFFFu, a01, d);
        float b10 = __shfl_up_sync(0xFFFFFFFFu, a10, d);
        float b11 = __shfl_up_sync(0xFFFFFFFFu, a11, d);
        if (lane >= d) {
            float n00 = fmaf(a00, b00, a01 * b10);   // mine(later)*other(earlier)
            float n01 = fmaf(a00, b01, a01 * b11);
            float n10 = fmaf(a10, b00, a11 * b10);
            float n11 = fmaf(a10, b01, a11 * b11);
            float r = __fdividef(1.0f, n00 + n01 + n10 + n11);
            a00 = n00 * r; a01 = n01 * r; a10 = n10 * r; a11 = n11 * r;
        }
    }

    // warp0 publishes its row's total (lane 31 inclusive) for warp1
    if (warpInRow == 0 && lane == 31)
        w0tot[rowInCta] = make_float4(a00, a01, a10, a11);

    // exclusive prefix within this warp
    float e00 = __shfl_up_sync(0xFFFFFFFFu, a00, 1);
    float e01 = __shfl_up_sync(0xFFFFFFFFu, a01, 1);
    float e10 = __shfl_up_sync(0xFFFFFFFFu, a10, 1);
    float e11 = __shfl_up_sync(0xFFFFFFFFu, a11, 1);
    if (lane == 0) { e00 = 1.f; e01 = 0.f; e10 = 0.f; e11 = 1.f; }

    __syncthreads();

    if (warpInRow == 1) {
        // full exclusive = excl(this warp) * warp0_total   (later * earlier)
        float4 w0 = w0tot[rowInCta];
        float n00 = fmaf(e00, w0.x, e01 * w0.z);
        float n01 = fmaf(e00, w0.y, e01 * w0.w);
        float n10 = fmaf(e10, w0.x, e11 * w0.z);
        float n11 = fmaf(e10, w0.y, e11 * w0.w);
        e00 = n00; e01 = n01; e10 = n10; e11 = n11;
    }

    // state at this lane's segment start
    float hu0 = 1.0f - pL0;
    float hm0 = pL0;
    float hu = fmaf(e00, hu0, e01 * hm0);
    float hm = fmaf(e10, hu0, e11 * hm0);
    float rs = __fdividef(1.0f, hu + hm);
    hu *= rs; hm *= rs;

    // ---- pass 2: replay segment, emit p_correct --------------------------
    float* op = out + s0;
#pragma unroll
    for (int q = 0; q < SEG / 4; ++q) {
        float4 res;
        float* r4 = reinterpret_cast<float*>(&res);
#pragma unroll
        for (int j = 0; j < 4; ++j) {
            const int i = 4 * q + j;
            float nm = fmaf(C1[i], hm, C2[i] * hu);
            float nu = fmaf(C3[i], hm, C4[i] * hu);
            float r  = __fdividef(1.0f, nm + nu);
            hm = nm * r;
            hu = nu * r;
            bool o = (obits >> i) & 1u;
            float pom = C1[i] + C3[i];             // = 1-pS if o else pS
            float pou = C2[i] + C4[i];             // = pG   if o else 1-pG
            float c5 = o ? pom : (1.0f - pom);     // 1-pS
            float c6 = o ? pou : (1.0f - pou);     // pG
            r4[j] = fmaf(c5, hm, c6 * hu);
        }
        *reinterpret_cast<float4*>(op + 4 * q) = res;
    }
}

extern "C" void kernel_launch(void* const* d_in, const int* in_sizes, int n_in,
                              void* d_out, int out_size) {
    const float* pL0 = (const float*)d_in[0];
    const float* pT  = (const float*)d_in[1];
    const float* pF  = (const float*)d_in[2];
    const float* pG  = (const float*)d_in[3];
    const float* pS  = (const float*)d_in[4];
    const float* om  = (const float*)d_in[5];
    const float* sg  = (const float*)d_in[6];
    const float4* ab = (const float4*)d_in[7];
    const int* obs = (const int*)d_in[8];
    const int* kc  = (const int*)d_in[9];
    const int* pid = (const int*)d_in[10];
    const int* sid = (const int*)d_in[11];
    float* out = (float*)d_out;

    int K = in_sizes[0];                  // 1000
    int P = in_sizes[5];                  // 50000
    int B = in_sizes[8] / T_LEN;          // 8192 rows
    if (K > K_CAP) K = K_CAP;
    if (P > P_CAP) P = P_CAP;

    int n = (K > P) ? K : P;
    if (n < 1) n = 1;
    pack_tables<<<(n + 511) / 512, 512>>>(pT, pF, pG, pS, om, sg, K, P);

    int grid = (B + ROWS_PER_CTA - 1) / ROWS_PER_CTA;   // 2048
    bkt_warp_scan<<<grid, THREADS>>>(pL0, ab, obs, kc, pid, sid, out, B, K);
}

// round 12
// speedup vs baseline: 1.4303x; 1.0697x over previous
#include <cuda_runtime.h>
#include <cuda_fp16.h>
#include <cstdint>

// SuperchargingBKT — round 11: cut latency slack over the L1-wavefront floor.
//
// Model (fits R2-R10): ~35-40us of the runtime is irreducible l1tex wavefront
// processing for the two random gathers; the rest is slack from dependent
// MUFU chains (sigmoid = ex2->rcp) and the serialized pack pre-kernel.
// R11: (1) sigmoid via single-MUFU tanh.approx; (2) kc table staged in smem
// straight from source arrays (pack kernel now pshalf-only, ~1.5us);
// (3) 3 CTAs/SM to keep the L1 pipe fed.
//
// Inputs (metadata order):
//  0 pL0_logit [K] f32   4 pS_logit [K] f32    8 observations [B,T] i32
//  1 pT_logit  [K] f32   5 omega    [P] f32    9 kc_ids       [B,T] i32
//  2 pF_logit  [K] f32   6 sigma    [P] f32   10 problem_ids  [B,T] i32
//  3 pG_logit  [K] f32   7 ability  [S,4] f32 11 student_ids  [B,T] i32
// Output: p_correct [B,T] f32

constexpr int T_LEN = 512;
constexpr int SEG   = 8;               // steps per lane (2 warps x 32 x 8)
constexpr int HALF  = 256;             // steps per warp
constexpr int THREADS = 256;           // 8 warps = 4 rows per CTA
constexpr int ROWS_PER_CTA = 4;
constexpr int K_CAP = 1024;            // K = 1000
constexpr int P_CAP = 50048;           // P = 50000

__device__ __half2 g_pshalf[P_CAP];    // (omega,sigma) per problem, fp16

// single-MUFU sigmoid: sigma(x) = 0.5*tanh(0.5x) + 0.5
__device__ __forceinline__ float sigmoidf(float x) {
    float t;
    asm("tanh.approx.f32 %0, %1;" : "=f"(t) : "f"(x * 0.5f));
    return fmaf(t, 0.5f, 0.5f);
}

__global__ void pack_ps(
    const float* __restrict__ omega, const float* __restrict__ sigma, int P)
{
    int i = blockIdx.x * blockDim.x + threadIdx.x;
    if (i < P)
        g_pshalf[i] = __floats2half2_rn(omega[i], sigma[i]);
}

__global__ void __launch_bounds__(THREADS, 3)
bkt_warp_scan(
    const float* __restrict__ pL0_logit,
    const float* __restrict__ pT_logit,
    const float* __restrict__ pF_logit,
    const float* __restrict__ pG_logit,
    const float* __restrict__ pS_logit,
    const float4* __restrict__ ability,
    const int*  __restrict__ obs,
    const int*  __restrict__ kc,
    const int*  __restrict__ pid,
    const int*  __restrict__ sid,
    float* __restrict__ out,
    int B, int K)
{
    __shared__ float4 kcTab[K_CAP];              // 16KB
    __shared__ float4 w0tot[ROWS_PER_CTA];       // warp0 total matrix per row

    const int tid  = threadIdx.x;
    const int lane = tid & 31;
    const int wid  = tid >> 5;                   // 0..7
    const int rowInCta  = wid >> 1;              // 0..3
    const int warpInRow = wid & 1;               // 0 = steps 0-255, 1 = 256-511
    const int row  = blockIdx.x * ROWS_PER_CTA + rowInCta;

    // stage kc table directly from source arrays (coalesced, L2-hot)
    for (int i = tid; i < K; i += THREADS)
        kcTab[i] = make_float4(pT_logit[i], pF_logit[i], pG_logit[i], pS_logit[i]);
    __syncthreads();

    const int base = row * T_LEN;
    const int s0   = base + warpInRow * HALF + lane * SEG;

    // ---- front-load ALL indices and gathers for this lane's 8 steps ------
    int4 kv0 = *reinterpret_cast<const int4*>(kc  + s0);
    int4 kv1 = *reinterpret_cast<const int4*>(kc  + s0 + 4);
    int4 pv0 = *reinterpret_cast<const int4*>(pid + s0);
    int4 pv1 = *reinterpret_cast<const int4*>(pid + s0 + 4);
    int4 sv0 = *reinterpret_cast<const int4*>(sid + s0);
    int4 sv1 = *reinterpret_cast<const int4*>(sid + s0 + 4);
    int4 ov0 = *reinterpret_cast<const int4*>(obs + s0);
    int4 ov1 = *reinterpret_cast<const int4*>(obs + s0 + 4);

    int kk[SEG] = {kv0.x, kv0.y, kv0.z, kv0.w, kv1.x, kv1.y, kv1.z, kv1.w};
    int pp[SEG] = {pv0.x, pv0.y, pv0.z, pv0.w, pv1.x, pv1.y, pv1.z, pv1.w};
    int ssx[SEG]= {sv0.x, sv0.y, sv0.z, sv0.w, sv1.x, sv1.y, sv1.z, sv1.w};
    unsigned obits = 0;
    {
        int oo[SEG] = {ov0.x, ov0.y, ov0.z, ov0.w, ov1.x, ov1.y, ov1.z, ov1.w};
#pragma unroll
        for (int i = 0; i < SEG; ++i) obits |= (oo[i] != 0 ? 1u : 0u) << i;
    }

    float4  th[SEG];
    __half2 ph[SEG];
#pragma unroll
    for (int i = 0; i < SEG; ++i) th[i] = __ldg(ability + ssx[i]);   // 8 in flight
#pragma unroll
    for (int i = 0; i < SEG; ++i) ph[i] = __ldg(&g_pshalf[pp[i]]);

    // initial state from pL0 at first KC (uniform broadcast load)
    float pL0 = sigmoidf(__ldg(pL0_logit + __ldg(kc + base)));

    // ---- pass 1: coefficients + per-lane segment matrix product ----------
    float C1[SEG], C2[SEG], C3[SEG], C4[SEG];
    float a00 = 1.f, a01 = 0.f, a10 = 0.f, a11 = 1.f;
#pragma unroll
    for (int i = 0; i < SEG; ++i) {
        float4 kcp = kcTab[kk[i]];               // LDS.128
        float2 psp = __half22float2(ph[i]);
        float pT = sigmoidf(kcp.x + th[i].x);
        float pF = sigmoidf(kcp.y - th[i].y);
        float pG = sigmoidf(kcp.z + psp.x + th[i].z);
        float pS = sigmoidf(kcp.w + psp.y - th[i].w);
        bool o = (obits >> i) & 1u;
        float pom = o ? (1.0f - pS) : pS;        // P(y | mastered)
        float pou = o ? pG : (1.0f - pG);        // P(y | unmastered)
        float c1 = (1.0f - pF) * pom;
        float c2 = pT * pou;
        float c3 = pF * pom;
        float c4 = (1.0f - pT) * pou;
        C1[i] = c1; C2[i] = c2; C3[i] = c3; C4[i] = c4;

        // A = M * A,  M = [[c4,c3],[c2,c1]]
        float n00 = fmaf(c4, a00, c3 * a10);
        float n01 = fmaf(c4, a01, c3 * a11);
        float n10 = fmaf(c2, a00, c1 * a10);
        float n11 = fmaf(c2, a01, c1 * a11);
        a00 = n00; a01 = n01; a10 = n10; a11 = n11;
    }
    {   // one normalization per 8-step segment
        float r = __fdividef(1.0f, a00 + a01 + a10 + a11);
        a00 *= r; a01 *= r; a10 *= r; a11 *= r;
    }

    // ---- inclusive warp scan of segment matrices -------------------------
#pragma unroll
    for (int d = 1; d < 32; d <<= 1) {
        float b00 = __shfl_up_sync(0xFFFFFFFFu, a00, d);
        float b01 = __shfl_up_sync(0xFFFFFFFFu, a01, d);
        float b10 = __shfl_up_sync(0xFFFFFFFFu, a10, d);
        float b11 = __shfl_up_sync(0xFFFFFFFFu, a11, d);
        if (lane >= d) {
            float n00 = fmaf(a00, b00, a01 * b10);   // mine(later)*other(earlier)
            float n01 = fmaf(a00, b01, a01 * b11);
            float n10 = fmaf(a10, b00, a11 * b10);
            float n11 = fmaf(a10, b01, a11 * b11);
            float r = __fdividef(1.0f, n00 + n01 + n10 + n11);
            a00 = n00 * r; a01 = n01 * r; a10 = n10 * r; a11 = n11 * r;
        }
    }

    // warp0 publishes its row's total (lane 31 inclusive) for warp1
    if (warpInRow == 0 && lane == 31)
        w0tot[rowInCta] = make_float4(a00, a01, a10, a11);

    // exclusive prefix within this warp
    float e00 = __shfl_up_sync(0xFFFFFFFFu, a00, 1);
    float e01 = __shfl_up_sync(0xFFFFFFFFu, a01, 1);
    float e10 = __shfl_up_sync(0xFFFFFFFFu, a10, 1);
    float e11 = __shfl_up_sync(0xFFFFFFFFu, a11, 1);
    if (lane == 0) { e00 = 1.f; e01 = 0.f; e10 = 0.f; e11 = 1.f; }

    __syncthreads();

    if (warpInRow == 1) {
        // full exclusive = excl(this warp) * warp0_total   (later * earlier)
        float4 w0 = w0tot[rowInCta];
        float n00 = fmaf(e00, w0.x, e01 * w0.z);
        float n01 = fmaf(e00, w0.y, e01 * w0.w);
        float n10 = fmaf(e10, w0.x, e11 * w0.z);
        float n11 = fmaf(e10, w0.y, e11 * w0.w);
        e00 = n00; e01 = n01; e10 = n10; e11 = n11;
    }

    // state at this lane's segment start
    float hu0 = 1.0f - pL0;
    float hm0 = pL0;
    float hu = fmaf(e00, hu0, e01 * hm0);
    float hm = fmaf(e10, hu0, e11 * hm0);
    float rs = __fdividef(1.0f, hu + hm);
    hu *= rs; hm *= rs;

    // ---- pass 2: replay segment, emit p_correct --------------------------
    float* op = out + s0;
#pragma unroll
    for (int q = 0; q < SEG / 4; ++q) {
        float4 res;
        float* r4 = reinterpret_cast<float*>(&res);
#pragma unroll
        for (int j = 0; j < 4; ++j) {
            const int i = 4 * q + j;
            float nm = fmaf(C1[i], hm, C2[i] * hu);
            float nu = fmaf(C3[i], hm, C4[i] * hu);
            float r  = __fdividef(1.0f, nm + nu);
            hm = nm * r;
            hu = nu * r;
            bool o = (obits >> i) & 1u;
            float pom = C1[i] + C3[i];             // = 1-pS if o else pS
            float pou = C2[i] + C4[i];             // = pG   if o else 1-pG
            float c5 = o ? pom : (1.0f - pom);     // 1-pS
            float c6 = o ? pou : (1.0f - pou);     // pG
            r4[j] = fmaf(c5, hm, c6 * hu);
        }
        *reinterpret_cast<float4*>(op + 4 * q) = res;
    }
}

extern "C" void kernel_launch(void* const* d_in, const int* in_sizes, int n_in,
                              void* d_out, int out_size) {
    const float* pL0 = (const float*)d_in[0];
    const float* pT  = (const float*)d_in[1];
    const float* pF  = (const float*)d_in[2];
    const float* pG  = (const float*)d_in[3];
    const float* pS  = (const float*)d_in[4];
    const float* om  = (const float*)d_in[5];
    const float* sg  = (const float*)d_in[6];
    const float4* ab = (const float4*)d_in[7];
    const int* obs = (const int*)d_in[8];
    const int* kc  = (const int*)d_in[9];
    const int* pid = (const int*)d_in[10];
    const int* sid = (const int*)d_in[11];
    float* out = (float*)d_out;

    int K = in_sizes[0];                  // 1000
    int P = in_sizes[5];                  // 50000
    int B = in_sizes[8] / T_LEN;          // 8192 rows
    if (K > K_CAP) K = K_CAP;
    if (P > P_CAP) P = P_CAP;

    pack_ps<<<(P + 511) / 512, 512>>>(om, sg, P);

    int grid = (B + ROWS_PER_CTA - 1) / ROWS_PER_CTA;   // 2048
    bkt_warp_scan<<<grid, THREADS>>>(pL0, pT, pF, pG, pS, ab,
                                     obs, kc, pid, sid, out, B, K);
}